// round 6
// baseline (speedup 1.0000x reference)
#include <cuda_runtime.h>

#define NN 3000
#define TT 20
#define IND 6
#define HD 64
#define NH 8
#define MAXNZ 512

// ---------------- scratch (no allocation allowed) ----------------
__device__ float2 g_Whh2[HD * 192];         // recurrent weights, duplicated pairs [k][row]
__device__ float g_support[NN * HD];        // GRU final hidden
__device__ float g_s[2][NN * HD];           // per-graph head features  [n][h*8+f]
__device__ float g_f1[2][NH * NN];          // source scores  [g][h*N+n]
__device__ float g_f2[2][NH * NN];          // dest scores    [g][h*N+n]
__device__ unsigned g_f1maxI[16];           // encoded global per-(g,h) max of f1
__device__ float g_att[2][NN * HD];         // attention outputs
__device__ float g_emb[NN * HD];            // pre-pairnorm embedding
__device__ float g_colsum[HD];              // column sums for pairnorm mean

__device__ __forceinline__ float sigm(float x) { return 1.0f / (1.0f + __expf(-x)); }
__device__ __forceinline__ float tanhfast(float x) { return 2.0f * sigm(2.0f * x) - 1.0f; }

// order-preserving float<->uint encoding for atomicMax
__device__ __forceinline__ unsigned fenc(float f) {
    unsigned u = __float_as_uint(f);
    return (u & 0x80000000u) ? ~u : (u | 0x80000000u);
}
__device__ __forceinline__ float fdec(unsigned u) {
    return __uint_as_float((u & 0x80000000u) ? (u & 0x7fffffffu) : ~u);
}

// packed f32x2 helpers
__device__ __forceinline__ unsigned long long pk(float lo, float hi) {
    unsigned long long r;
    asm("mov.b64 %0, {%1,%2};" : "=l"(r) : "f"(lo), "f"(hi));
    return r;
}
__device__ __forceinline__ void upk(unsigned long long v, float& lo, float& hi) {
    asm("mov.b64 {%0,%1}, %2;" : "=f"(lo), "=f"(hi) : "l"(v));
}
__device__ __forceinline__ void ffma2(unsigned long long& d, unsigned long long a, unsigned long long b) {
    asm("fma.rn.f32x2 %0, %1, %2, %0;" : "+l"(d) : "l"(a), "l"(b));
}

// ---------------- K0: duplicate Whh pairs + init reductions ----------------
__global__ void prep_kernel(const float* __restrict__ Whh) {
    int i = blockIdx.x * 256 + threadIdx.x;
    if (i < 192 * HD) {
        int r = i >> 6, k = i & 63;
        float w = Whh[i];
        g_Whh2[k * 192 + r] = make_float2(w, w);
    }
    if (blockIdx.x == 0 && threadIdx.x < HD) g_colsum[threadIdx.x] = 0.f;
    if (blockIdx.x == 0 && threadIdx.x < 16) g_f1maxI[threadIdx.x] = 0u;
}

// ---------------- K1: GRU gate-split (192 thr = 1/gate-row, 4 nodes/block) + fused tail ----------------
__global__ void __launch_bounds__(192) gru_kernel(
        const float* __restrict__ x, const float* __restrict__ Wih,
        const float* __restrict__ bih, const float* __restrict__ bhh,
        const float* __restrict__ Wp, const float* __restrict__ Wn,
        const float* __restrict__ Wup, const float* __restrict__ Wvp,
        const float* __restrict__ Wun, const float* __restrict__ Wvn) {
    __shared__ float4 shh4[HD];            // [k] -> 4 nodes hidden
    __shared__ float4 shx4[IND];           // [c] -> 4 nodes input
    __shared__ ulonglong2 sgi[192];        // input-part gate accs (pairs: nodes01, nodes23)
    __shared__ ulonglong2 sgh[192];        // hidden-part gate accs
    float* shxf = (float*)shx4;
    int tid = threadIdx.x;                 // gate row 0..191 (r:0-63, z:64-127, n:128-191)
    int node0 = blockIdx.x * 4;            // 750 blocks

    unsigned long long pw[IND];
#pragma unroll
    for (int c = 0; c < IND; c++) {
        float w = Wih[tid * IND + c];
        pw[c] = pk(w, w);
    }
    float bi = bih[tid], bh = bhh[tid];
    unsigned long long pbi = pk(bi, bi), pbh = pk(bh, bh);

    if (tid < HD) shh4[tid] = make_float4(0.f, 0.f, 0.f, 0.f);
    float h0 = 0.f, h1 = 0.f, h2 = 0.f, h3 = 0.f;   // live in threads < 64 only

    const unsigned long long* w2 = (const unsigned long long*)g_Whh2;

    for (int t = 0; t < TT; t++) {
        if (tid < 24) {
            int c = tid >> 2, b = tid & 3;
            shxf[c * 4 + b] = x[((node0 + b) * TT + t) * IND + c];
        }
        __syncthreads();   // B1: shx ready, prev-step shh4 visible

        unsigned long long ai01 = pbi, ai23 = pbi;   // input part (incl bih)
        unsigned long long ah01 = pbh, ah23 = pbh;   // hidden part (incl bhh)

#pragma unroll
        for (int c = 0; c < IND; c++) {
            float4 xv = shx4[c];
            unsigned long long x01 = pk(xv.x, xv.y), x23 = pk(xv.z, xv.w);
            ffma2(ai01, pw[c], x01);
            ffma2(ai23, pw[c], x23);
        }
#pragma unroll 8
        for (int k = 0; k < HD; k++) {
            float4 hv = shh4[k];
            unsigned long long h01 = pk(hv.x, hv.y), h23 = pk(hv.z, hv.w);
            unsigned long long w = w2[k * 192 + tid];
            ffma2(ah01, w, h01);
            ffma2(ah23, w, h23);
        }
        sgi[tid] = make_ulonglong2(ai01, ai23);
        sgh[tid] = make_ulonglong2(ah01, ah23);
        __syncthreads();   // B2: all gate parts written; all shh4 reads done

        if (tid < 64) {
            ulonglong2 ri = sgi[tid],        rh = sgh[tid];
            ulonglong2 zi = sgi[64 + tid],   zh = sgh[64 + tid];
            ulonglong2 ni = sgi[128 + tid],  nh = sgh[128 + tid];
            float ir0, ir1, ir2, ir3, hr0, hr1, hr2, hr3;
            float iz0, iz1, iz2, iz3, hz0, hz1, hz2, hz3;
            float in0, in1, in2, in3, hn0, hn1, hn2, hn3;
            upk(ri.x, ir0, ir1); upk(ri.y, ir2, ir3);
            upk(rh.x, hr0, hr1); upk(rh.y, hr2, hr3);
            upk(zi.x, iz0, iz1); upk(zi.y, iz2, iz3);
            upk(zh.x, hz0, hz1); upk(zh.y, hz2, hz3);
            upk(ni.x, in0, in1); upk(ni.y, in2, in3);
            upk(nh.x, hn0, hn1); upk(nh.y, hn2, hn3);
            float r0 = sigm(ir0 + hr0), r1 = sigm(ir1 + hr1);
            float r2 = sigm(ir2 + hr2), r3 = sigm(ir3 + hr3);
            float z0 = sigm(iz0 + hz0), z1 = sigm(iz1 + hz1);
            float z2 = sigm(iz2 + hz2), z3 = sigm(iz3 + hz3);
            float n0 = tanhfast(in0 + r0 * hn0);
            float n1 = tanhfast(in1 + r1 * hn1);
            float n2 = tanhfast(in2 + r2 * hn2);
            float n3 = tanhfast(in3 + r3 * hn3);
            h0 = (1.f - z0) * n0 + z0 * h0;
            h1 = (1.f - z1) * n1 + z1 * h1;
            h2 = (1.f - z2) * n2 + z2 * h2;
            h3 = (1.f - z3) * n3 + z3 * h3;
            shh4[tid] = make_float4(h0, h1, h2, h3);
        }
        // no barrier here: next iteration's B1 (or final barrier) covers visibility
    }
    __syncthreads();   // final h visible to all

    if (tid < 64) {
        g_support[(node0 + 0) * HD + tid] = h0;
        g_support[(node0 + 1) * HD + tid] = h1;
        g_support[(node0 + 2) * HD + tid] = h2;
        g_support[(node0 + 3) * HD + tid] = h3;
    }

    // ------ fused head projection: threads 0-63 -> graph 0, 64-127 -> graph 1 ------
    if (tid < 128) {
        int g = tid >> 6, j = tid & 63;
        int hh = j >> 3, f = j & 7;
        const float* W  = g ? Wn  : Wp;
        float wu = (g ? Wun : Wup)[hh * 8 + f];
        float wv = (g ? Wvn : Wvp)[hh * 8 + f];
        const float* hsm = (const float*)shh4;   // [k*4 + b]
        float acc[4] = {0.f, 0.f, 0.f, 0.f};
#pragma unroll 4
        for (int k = 0; k < HD; k++) {
            float w = W[k * HD + j];
#pragma unroll
            for (int b = 0; b < 4; b++) acc[b] += hsm[k * 4 + b] * w;
        }
#pragma unroll
        for (int b = 0; b < 4; b++) {
            int n = node0 + b;
            g_s[g][n * HD + j] = acc[b];
            float t1 = acc[b] * wu, t2 = acc[b] * wv;
#pragma unroll
            for (int o = 4; o; o >>= 1) {
                t1 += __shfl_xor_sync(0xffffffffu, t1, o);
                t2 += __shfl_xor_sync(0xffffffffu, t2, o);
            }
            if (f == 0) {
                g_f1[g][hh * NN + n] = t1;
                g_f2[g][hh * NN + n] = t2;
                atomicMax(&g_f1maxI[g * 8 + hh], fenc(t1));
            }
        }
    }
}

// ---------------- K3: sparse masked attention, single pass (grid: [N, 2]) ----------------
__global__ void attn_kernel(const float* __restrict__ adj0, const float* __restrict__ adj1) {
    int i = blockIdx.x, g = blockIdx.y;
    const float* row = (g ? adj1 : adj0) + (size_t)i * NN;
    __shared__ int cnt;
    __shared__ short idx[MAXNZ];
    int tid = threadIdx.x, lane = tid & 31;
    if (tid == 0) cnt = 0;

    // prefetch the whole row slice to registers (MLP=3) before compaction
    const float4* row4 = (const float4*)row;   // N=3000 divisible by 4
    float4 v[3];
#pragma unroll
    for (int it = 0; it < 3; it++) {
        int q = it * 256 + tid;
        v[it] = (q < NN / 4) ? row4[q] : make_float4(0.f, 0.f, 0.f, 0.f);
    }
    __syncthreads();

#pragma unroll
    for (int it = 0; it < 3; it++) {
        int q = it * 256 + tid;
#pragma unroll
        for (int c = 0; c < 4; c++) {
            float val = (c == 0) ? v[it].x : (c == 1) ? v[it].y : (c == 2) ? v[it].z : v[it].w;
            unsigned bal = __ballot_sync(0xffffffffu, val != 0.f);
            if (bal) {
                int leader = __ffs(bal) - 1;
                int base;
                if (lane == leader) base = atomicAdd(&cnt, __popc(bal));
                base = __shfl_sync(0xffffffffu, base, leader);
                if (val != 0.f) {
                    int p = base + __popc(bal & ((1u << lane) - 1u));
                    if (p < MAXNZ) idx[p] = (short)(4 * q + c);
                }
            }
        }
    }
    __syncthreads();
    int m = min(cnt, MAXNZ);

    int h = tid >> 5;                         // warp = head
    const float* f1h = g_f1[g] + h * NN;
    float f2v = g_f2[g][h * NN + i];
    // shift M >= max over row nonzeros (leaky monotone; softmax shift-invariant)
    float Mv = fdec(g_f1maxI[g * 8 + h]) + f2v;
    Mv = Mv >= 0.f ? Mv : 0.2f * Mv;
    const float* sb = g_s[g];

    float se = 0.f;
    float acc[8] = {0, 0, 0, 0, 0, 0, 0, 0};
    for (int k = lane; k < m; k += 32) {
        int j = idx[k];
        float vv = f1h[j] + f2v;
        vv = vv >= 0.f ? vv : 0.2f * vv;
        float e = __expf(vv - Mv);
        se += e;
        const float4* sp = (const float4*)(sb + j * HD + h * 8);
        float4 a = sp[0], bb = sp[1];
        acc[0] += e * a.x;  acc[1] += e * a.y;  acc[2] += e * a.z;  acc[3] += e * a.w;
        acc[4] += e * bb.x; acc[5] += e * bb.y; acc[6] += e * bb.z; acc[7] += e * bb.w;
    }
#pragma unroll
    for (int o = 16; o; o >>= 1) {
        se += __shfl_xor_sync(0xffffffffu, se, o);
#pragma unroll
        for (int f = 0; f < 8; f++) acc[f] += __shfl_xor_sync(0xffffffffu, acc[f], o);
    }
    if (lane == 0) {
        float inv = se > 0.f ? 1.0f / se : 0.f;   // empty row -> zeros (matches ref mask)
        float* o2 = g_att[g] + i * HD + h * 8;
#pragma unroll
        for (int f = 0; f < 8; f++) o2[f] = acc[f] * inv;
    }
}

// ---------------- K4: warp-per-node residual/proj + MLPs + semantic attention ----------------
// grid: N/8 = 375, block 256 (8 warps x 1 node)
__global__ void __launch_bounds__(256) comb_kernel(
        const float* __restrict__ pos_b, const float* __restrict__ pWp, const float* __restrict__ pbp,
        const float* __restrict__ neg_b, const float* __restrict__ pWn, const float* __restrict__ pbn,
        const float* __restrict__ selfW, const float* __restrict__ selfb,
        const float* __restrict__ mpW, const float* __restrict__ mpb,
        const float* __restrict__ mnW, const float* __restrict__ mnb,
        const float* __restrict__ semW1, const float* __restrict__ semb1,
        const float* __restrict__ semW2) {
    __shared__ float sb[8][6][HD];     // per-warp staging: sup, ps, ns, e0, e1, e2
    __shared__ float colacc[HD];
    int tid = threadIdx.x, warp = tid >> 5, lane = tid & 31;
    int n = blockIdx.x * 8 + warp;     // 375*8 = 3000 exact
    int c0 = lane, c1 = lane + 32;

    if (tid < HD) colacc[tid] = 0.f;
    __syncthreads();

    float (*S)[HD] = sb[warp];
    S[0][c0] = g_support[n * HD + c0];
    S[0][c1] = g_support[n * HD + c1];
    __syncwarp();

    // ---- phase 1: ap = att0 + b + proj, an = att1 + b + proj, sv = self ----
    float ap0 = g_att[0][n * HD + c0] + pos_b[c0] + pbp[c0];
    float ap1 = g_att[0][n * HD + c1] + pos_b[c1] + pbp[c1];
    float an0 = g_att[1][n * HD + c0] + neg_b[c0] + pbn[c0];
    float an1 = g_att[1][n * HD + c1] + neg_b[c1] + pbn[c1];
    float sv0 = selfb[c0], sv1 = selfb[c1];
#pragma unroll 4
    for (int k = 0; k < HD; k++) {
        float s = S[0][k];
        ap0 += s * pWp[k * HD + c0];   ap1 += s * pWp[k * HD + c1];
        an0 += s * pWn[k * HD + c0];   an1 += s * pWn[k * HD + c1];
        sv0 += s * selfW[k * HD + c0]; sv1 += s * selfW[k * HD + c1];
    }
    S[1][c0] = ap0; S[1][c1] = ap1;
    S[2][c0] = an0; S[2][c1] = an1;
    __syncwarp();

    // ---- phase 2: sp = ps @ mpW + mpb, sn = ns @ mnW + mnb ----
    float sp0 = mpb[c0], sp1 = mpb[c1];
    float sn0 = mnb[c0], sn1 = mnb[c1];
#pragma unroll 4
    for (int k = 0; k < HD; k++) {
        float p = S[1][k], q = S[2][k];
        sp0 += p * mpW[k * HD + c0]; sp1 += p * mpW[k * HD + c1];
        sn0 += q * mnW[k * HD + c0]; sn1 += q * mnW[k * HD + c1];
    }
    S[3][c0] = sv0; S[3][c1] = sv1;
    S[4][c0] = sp0; S[4][c1] = sp1;
    S[5][c0] = sn0; S[5][c1] = sn1;
    __syncwarp();

    // ---- phase 3: semantic attention logits ----
    float t00 = semb1[c0], t01 = semb1[c1];
    float t10 = t00, t11 = t01, t20 = t00, t21 = t01;
#pragma unroll 4
    for (int k = 0; k < HD; k++) {
        float w0 = semW1[k * HD + c0], w1 = semW1[k * HD + c1];
        float a = S[3][k], b = S[4][k], c = S[5][k];
        t00 += a * w0; t01 += a * w1;
        t10 += b * w0; t11 += b * w1;
        t20 += c * w0; t21 += c * w1;
    }
    float w2v0 = semW2[c0], w2v1 = semW2[c1];
    float u0 = tanhfast(t00) * w2v0 + tanhfast(t01) * w2v1;
    float u1 = tanhfast(t10) * w2v0 + tanhfast(t11) * w2v1;
    float u2 = tanhfast(t20) * w2v0 + tanhfast(t21) * w2v1;
#pragma unroll
    for (int o = 16; o; o >>= 1) {
        u0 += __shfl_xor_sync(0xffffffffu, u0, o);
        u1 += __shfl_xor_sync(0xffffffffu, u1, o);
        u2 += __shfl_xor_sync(0xffffffffu, u2, o);
    }
    float mw = fmaxf(u0, fmaxf(u1, u2));
    float e0 = __expf(u0 - mw), e1 = __expf(u1 - mw), e2 = __expf(u2 - mw);
    float inv = 1.f / (e0 + e1 + e2);
    float emb0 = (e0 * sv0 + e1 * sp0 + e2 * sn0) * inv;
    float emb1 = (e0 * sv1 + e1 * sp1 + e2 * sn1) * inv;

    g_emb[n * HD + c0] = emb0;
    g_emb[n * HD + c1] = emb1;
    atomicAdd(&colacc[c0], emb0);
    atomicAdd(&colacc[c1], emb1);
    __syncthreads();
    if (tid < HD) atomicAdd(&g_colsum[tid], colacc[tid]);
}

// ---------------- K5: pairnorm + prediction head (warp per node) ----------------
__global__ void final_kernel(const float* __restrict__ predW, const float* __restrict__ predb,
                             float* __restrict__ out) {
    int warp = threadIdx.x >> 5, lane = threadIdx.x & 31;
    int n = blockIdx.x * 4 + warp;
    float invn = 1.0f / NN;
    float x0 = g_emb[n * HD + lane]      - g_colsum[lane]      * invn;
    float x1 = g_emb[n * HD + 32 + lane] - g_colsum[32 + lane] * invn;
    float ss = x0 * x0 + x1 * x1;
    float dt = x0 * predW[lane] + x1 * predW[32 + lane];
#pragma unroll
    for (int o = 16; o; o >>= 1) {
        ss += __shfl_xor_sync(0xffffffffu, ss, o);
        dt += __shfl_xor_sync(0xffffffffu, dt, o);
    }
    if (lane == 0) out[n] = sigm(dt * rsqrtf(1e-6f + ss) + predb[0]);
}

// ---------------- launch ----------------
extern "C" void kernel_launch(void* const* d_in, const int* in_sizes, int n_in,
                              void* d_out, int out_size) {
    (void)in_sizes; (void)n_in; (void)out_size;
    const float* inputs   = (const float*)d_in[0];
    const float* pos_adj  = (const float*)d_in[1];
    const float* neg_adj  = (const float*)d_in[2];
    const float* Wih      = (const float*)d_in[3];
    const float* Whh      = (const float*)d_in[4];
    const float* bih      = (const float*)d_in[5];
    const float* bhh      = (const float*)d_in[6];
    const float* pos_W    = (const float*)d_in[7];
    const float* pos_Wu   = (const float*)d_in[8];
    const float* pos_Wv   = (const float*)d_in[9];
    const float* pos_b    = (const float*)d_in[10];
    const float* pos_projW= (const float*)d_in[11];
    const float* pos_projb= (const float*)d_in[12];
    const float* neg_W    = (const float*)d_in[13];
    const float* neg_Wu   = (const float*)d_in[14];
    const float* neg_Wv   = (const float*)d_in[15];
    const float* neg_b    = (const float*)d_in[16];
    const float* neg_projW= (const float*)d_in[17];
    const float* neg_projb= (const float*)d_in[18];
    const float* self_W   = (const float*)d_in[19];
    const float* self_b   = (const float*)d_in[20];
    const float* mlpp_W   = (const float*)d_in[21];
    const float* mlpp_b   = (const float*)d_in[22];
    const float* mlpn_W   = (const float*)d_in[23];
    const float* mlpn_b   = (const float*)d_in[24];
    const float* sem_W1   = (const float*)d_in[25];
    const float* sem_b1   = (const float*)d_in[26];
    const float* sem_W2   = (const float*)d_in[27];
    const float* pred_W   = (const float*)d_in[28];
    const float* pred_b   = (const float*)d_in[29];

    prep_kernel<<<48, 256>>>(Whh);
    gru_kernel<<<NN / 4, 192>>>(inputs, Wih, bih, bhh,
                                pos_W, neg_W, pos_Wu, pos_Wv, neg_Wu, neg_Wv);
    attn_kernel<<<dim3(NN, 2), 256>>>(pos_adj, neg_adj);
    comb_kernel<<<NN / 8, 256>>>(pos_b, pos_projW, pos_projb, neg_b, neg_projW, neg_projb,
                                 self_W, self_b, mlpp_W, mlpp_b, mlpn_W, mlpn_b,
                                 sem_W1, sem_b1, sem_W2);
    final_kernel<<<NN / 4, 128>>>(pred_W, pred_b, (float*)d_out);
}

// round 7
// speedup vs baseline: 1.0878x; 1.0878x over previous
#include <cuda_runtime.h>

#define NN 3000
#define TT 20
#define IND 6
#define HD 64
#define NH 8
#define MAXNZ 512

// dynamic smem layout for gru: [ weights 96KB | shh4 2x64 float4 | shx 2x6 float4 ]
#define GRU_W_BYTES   (192 * HD * 8)                 // 98304
#define GRU_SHH_OFF   GRU_W_BYTES
#define GRU_SHX_OFF   (GRU_SHH_OFF + 2 * HD * 16)    // +2048
#define GRU_SMEM      (GRU_SHX_OFF + 2 * IND * 16)   // +192 = 100544

// ---------------- scratch (no allocation allowed) ----------------
__device__ float2 g_Whh2[HD * 192];         // recurrent weights, duplicated pairs [k][row]
__device__ float g_support[NN * HD];        // GRU final hidden
__device__ float g_s[2][NN * HD];           // per-graph head features  [n][h*8+f]
__device__ float g_f1[2][NH * NN];          // source scores  [g][h*N+n]
__device__ float g_f2[2][NH * NN];          // dest scores    [g][h*N+n]
__device__ unsigned g_f1maxI[16];           // encoded global per-(g,h) max of f1
__device__ float g_att[2][NN * HD];         // attention outputs
__device__ float g_emb[NN * HD];            // pre-pairnorm embedding
__device__ float g_colsum[HD];              // column sums for pairnorm mean

__device__ __forceinline__ float sigm(float x) { return 1.0f / (1.0f + __expf(-x)); }
__device__ __forceinline__ float tanhfast(float x) { return 2.0f * sigm(2.0f * x) - 1.0f; }

// order-preserving float<->uint encoding for atomicMax
__device__ __forceinline__ unsigned fenc(float f) {
    unsigned u = __float_as_uint(f);
    return (u & 0x80000000u) ? ~u : (u | 0x80000000u);
}
__device__ __forceinline__ float fdec(unsigned u) {
    return __uint_as_float((u & 0x80000000u) ? (u & 0x7fffffffu) : ~u);
}

// packed f32x2 helpers
__device__ __forceinline__ unsigned long long pk(float lo, float hi) {
    unsigned long long r;
    asm("mov.b64 %0, {%1,%2};" : "=l"(r) : "f"(lo), "f"(hi));
    return r;
}
__device__ __forceinline__ void upk(unsigned long long v, float& lo, float& hi) {
    asm("mov.b64 {%0,%1}, %2;" : "=f"(lo), "=f"(hi) : "l"(v));
}
__device__ __forceinline__ void ffma2(unsigned long long& d, unsigned long long a, unsigned long long b) {
    asm("fma.rn.f32x2 %0, %1, %2, %0;" : "+l"(d) : "l"(a), "l"(b));
}

// ---------------- K0: duplicate Whh pairs + init reductions ----------------
__global__ void prep_kernel(const float* __restrict__ Whh) {
    int i = blockIdx.x * 256 + threadIdx.x;
    if (i < 192 * HD) {
        int r = i >> 6, k = i & 63;
        float w = Whh[i];
        g_Whh2[k * 192 + r] = make_float2(w, w);
    }
    if (blockIdx.x == 0 && threadIdx.x < HD) g_colsum[threadIdx.x] = 0.f;
    if (blockIdx.x == 0 && threadIdx.x < 16) g_f1maxI[threadIdx.x] = 0u;
}

// ---------------- K1: GRU, weights in SMEM, 2 groups x 4 nodes / 128-thread block ----------------
__global__ void __launch_bounds__(128) gru_kernel(
        const float* __restrict__ x, const float* __restrict__ Wih,
        const float* __restrict__ bih, const float* __restrict__ bhh,
        const float* __restrict__ Wp, const float* __restrict__ Wn,
        const float* __restrict__ Wup, const float* __restrict__ Wvp,
        const float* __restrict__ Wun, const float* __restrict__ Wvn) {
    extern __shared__ unsigned char smem_raw[];
    unsigned long long* sW = (unsigned long long*)smem_raw;              // [k*192 + row]
    float4* shhAll = (float4*)(smem_raw + GRU_SHH_OFF);                  // [grp*64 + k]
    float*  shxAll = (float*)(smem_raw + GRU_SHX_OFF);                   // [grp*24 + c*4 + b]

    int tid = threadIdx.x;
    int grp = tid >> 6, j = tid & 63;
    int node0 = blockIdx.x * 8 + grp * 4;        // 375 blocks x 8 nodes
    float4* shh4 = shhAll + grp * HD;
    float*  shxf = shxAll + grp * 24;
    float4* shx4 = (float4*)shxf;

    // ---- stage weights into smem (96KB, whole block) ----
    {
        const float4* src = (const float4*)g_Whh2;
        float4* dst = (float4*)sW;
#pragma unroll
        for (int i = tid; i < 192 * HD / 2; i += 128) dst[i] = src[i];
    }

    unsigned long long pwr[IND], pwz[IND], pwn[IND];
#pragma unroll
    for (int c = 0; c < IND; c++) {
        float a = Wih[j * IND + c];
        float b = Wih[(64 + j) * IND + c];
        float d = Wih[(128 + j) * IND + c];
        pwr[c] = pk(a, a); pwz[c] = pk(b, b); pwn[c] = pk(d, d);
    }
    float br  = bih[j] + bhh[j];
    float bz  = bih[64 + j] + bhh[64 + j];
    float bin = bih[128 + j];
    float bhn = bhh[128 + j];
    unsigned long long pbr = pk(br, br), pbz = pk(bz, bz);
    unsigned long long pbi = pk(bin, bin), pbh = pk(bhn, bhn);

    shh4[j] = make_float4(0.f, 0.f, 0.f, 0.f);
    float h0 = 0.f, h1 = 0.f, h2 = 0.f, h3 = 0.f;
    __syncthreads();   // weights + zeroed shh visible

    for (int t = 0; t < TT; t++) {
        if (j < 24) {
            int c = j >> 2, b = j & 3;
            shxf[c * 4 + b] = x[((node0 + b) * TT + t) * IND + c];
        }
        __syncthreads();   // B1: shx ready; prev shh writes visible

        unsigned long long ar01 = pbr, ar23 = pbr;
        unsigned long long az01 = pbz, az23 = pbz;
        unsigned long long an01 = pbi, an23 = pbi;
        unsigned long long gn01 = pbh, gn23 = pbh;

#pragma unroll
        for (int c = 0; c < IND; c++) {
            float4 xv = shx4[c];
            unsigned long long x01 = pk(xv.x, xv.y), x23 = pk(xv.z, xv.w);
            ffma2(ar01, pwr[c], x01); ffma2(ar23, pwr[c], x23);
            ffma2(az01, pwz[c], x01); ffma2(az23, pwz[c], x23);
            ffma2(an01, pwn[c], x01); ffma2(an23, pwn[c], x23);
        }

#pragma unroll 4
        for (int k = 0; k < HD; k++) {
            float4 hv = shh4[k];
            unsigned long long h01 = pk(hv.x, hv.y), h23 = pk(hv.z, hv.w);
            unsigned long long w0 = sW[k * 192 + j];
            unsigned long long w1 = sW[k * 192 + 64 + j];
            unsigned long long wn2 = sW[k * 192 + 128 + j];
            ffma2(ar01, w0, h01);  ffma2(ar23, w0, h23);
            ffma2(az01, w1, h01);  ffma2(az23, w1, h23);
            ffma2(gn01, wn2, h01); ffma2(gn23, wn2, h23);
        }
        __syncthreads();   // B2: all reads of shh done before overwrite

        float a0, a1, a2, a3, z0, z1, z2, z3, n0, n1, n2, n3, g0, g1, g2, g3;
        upk(ar01, a0, a1); upk(ar23, a2, a3);
        upk(az01, z0, z1); upk(az23, z2, z3);
        upk(an01, n0, n1); upk(an23, n2, n3);
        upk(gn01, g0, g1); upk(gn23, g2, g3);

        float r0 = sigm(a0), r1 = sigm(a1), r2 = sigm(a2), r3 = sigm(a3);
        float zz0 = sigm(z0), zz1 = sigm(z1), zz2 = sigm(z2), zz3 = sigm(z3);
        float nv0 = tanhfast(n0 + r0 * g0);
        float nv1 = tanhfast(n1 + r1 * g1);
        float nv2 = tanhfast(n2 + r2 * g2);
        float nv3 = tanhfast(n3 + r3 * g3);
        h0 = (1.f - zz0) * nv0 + zz0 * h0;
        h1 = (1.f - zz1) * nv1 + zz1 * h1;
        h2 = (1.f - zz2) * nv2 + zz2 * h2;
        h3 = (1.f - zz3) * nv3 + zz3 * h3;
        shh4[j] = make_float4(h0, h1, h2, h3);
    }
    __syncthreads();   // h fully written before fused tail reads

    g_support[(node0 + 0) * HD + j] = h0;
    g_support[(node0 + 1) * HD + j] = h1;
    g_support[(node0 + 2) * HD + j] = h2;
    g_support[(node0 + 3) * HD + j] = h3;

    // ------ fused head projection per group: s = h @ W, f1/f2, global f1 max ------
    int hh = j >> 3, f = j & 7;
    const float* hsm = (const float*)shh4;   // [k*4 + b]
#pragma unroll
    for (int g = 0; g < 2; g++) {
        const float* W  = g ? Wn  : Wp;
        float wu = (g ? Wun : Wup)[hh * 8 + f];
        float wv = (g ? Wvn : Wvp)[hh * 8 + f];
        float acc[4] = {0.f, 0.f, 0.f, 0.f};
#pragma unroll 4
        for (int k = 0; k < HD; k++) {
            float w = W[k * HD + j];
#pragma unroll
            for (int b = 0; b < 4; b++) acc[b] += hsm[k * 4 + b] * w;
        }
#pragma unroll
        for (int b = 0; b < 4; b++) {
            int n = node0 + b;
            g_s[g][n * HD + j] = acc[b];
            float t1 = acc[b] * wu, t2 = acc[b] * wv;
#pragma unroll
            for (int o = 4; o; o >>= 1) {
                t1 += __shfl_xor_sync(0xffffffffu, t1, o);
                t2 += __shfl_xor_sync(0xffffffffu, t2, o);
            }
            if (f == 0) {
                g_f1[g][hh * NN + n] = t1;
                g_f2[g][hh * NN + n] = t2;
                atomicMax(&g_f1maxI[g * 8 + hh], fenc(t1));
            }
        }
    }
}

// ---------------- K3: sparse masked attention, single pass (grid: [N, 2]) ----------------
__global__ void attn_kernel(const float* __restrict__ adj0, const float* __restrict__ adj1) {
    int i = blockIdx.x, g = blockIdx.y;
    const float* row = (g ? adj1 : adj0) + (size_t)i * NN;
    __shared__ int cnt;
    __shared__ short idx[MAXNZ];
    int tid = threadIdx.x, lane = tid & 31;
    if (tid == 0) cnt = 0;

    // prefetch the whole row slice to registers (MLP=3) before compaction
    const float4* row4 = (const float4*)row;   // N=3000 divisible by 4
    float4 v[3];
#pragma unroll
    for (int it = 0; it < 3; it++) {
        int q = it * 256 + tid;
        v[it] = (q < NN / 4) ? row4[q] : make_float4(0.f, 0.f, 0.f, 0.f);
    }
    __syncthreads();

#pragma unroll
    for (int it = 0; it < 3; it++) {
        int q = it * 256 + tid;
#pragma unroll
        for (int c = 0; c < 4; c++) {
            float val = (c == 0) ? v[it].x : (c == 1) ? v[it].y : (c == 2) ? v[it].z : v[it].w;
            unsigned bal = __ballot_sync(0xffffffffu, val != 0.f);
            if (bal) {
                int leader = __ffs(bal) - 1;
                int base;
                if (lane == leader) base = atomicAdd(&cnt, __popc(bal));
                base = __shfl_sync(0xffffffffu, base, leader);
                if (val != 0.f) {
                    int p = base + __popc(bal & ((1u << lane) - 1u));
                    if (p < MAXNZ) idx[p] = (short)(4 * q + c);
                }
            }
        }
    }
    __syncthreads();
    int m = min(cnt, MAXNZ);

    int h = tid >> 5;                         // warp = head
    const float* f1h = g_f1[g] + h * NN;
    float f2v = g_f2[g][h * NN + i];
    // shift M >= max over row nonzeros (leaky monotone; softmax shift-invariant)
    float Mv = fdec(g_f1maxI[g * 8 + h]) + f2v;
    Mv = Mv >= 0.f ? Mv : 0.2f * Mv;
    const float* sb = g_s[g];

    float se = 0.f;
    float acc[8] = {0, 0, 0, 0, 0, 0, 0, 0};
    for (int k = lane; k < m; k += 32) {
        int j = idx[k];
        float vv = f1h[j] + f2v;
        vv = vv >= 0.f ? vv : 0.2f * vv;
        float e = __expf(vv - Mv);
        se += e;
        const float4* sp = (const float4*)(sb + j * HD + h * 8);
        float4 a = sp[0], bb = sp[1];
        acc[0] += e * a.x;  acc[1] += e * a.y;  acc[2] += e * a.z;  acc[3] += e * a.w;
        acc[4] += e * bb.x; acc[5] += e * bb.y; acc[6] += e * bb.z; acc[7] += e * bb.w;
    }
#pragma unroll
    for (int o = 16; o; o >>= 1) {
        se += __shfl_xor_sync(0xffffffffu, se, o);
#pragma unroll
        for (int f = 0; f < 8; f++) acc[f] += __shfl_xor_sync(0xffffffffu, acc[f], o);
    }
    if (lane == 0) {
        float inv = se > 0.f ? 1.0f / se : 0.f;   // empty row -> zeros (matches ref mask)
        float* o2 = g_att[g] + i * HD + h * 8;
#pragma unroll
        for (int f = 0; f < 8; f++) o2[f] = acc[f] * inv;
    }
}

// ---------------- K4: warp-per-2-nodes, float2 channel pairing (grid: N/8, block 128) ----------------
__global__ void __launch_bounds__(128) comb_kernel(
        const float* __restrict__ pos_b, const float* __restrict__ pWp, const float* __restrict__ pbp,
        const float* __restrict__ neg_b, const float* __restrict__ pWn, const float* __restrict__ pbn,
        const float* __restrict__ selfW, const float* __restrict__ selfb,
        const float* __restrict__ mpW, const float* __restrict__ mpb,
        const float* __restrict__ mnW, const float* __restrict__ mnb,
        const float* __restrict__ semW1, const float* __restrict__ semb1,
        const float* __restrict__ semW2) {
    __shared__ float sb[4][12][HD];     // per-warp staging
    __shared__ float colacc[HD];
    int tid = threadIdx.x, warp = tid >> 5, lane = tid & 31;
    int nA = blockIdx.x * 8 + warp * 2;   // 375*8 = 3000 exact
    int nB = nA + 1;
    int c0 = 2 * lane, c1 = 2 * lane + 1;

    if (tid < HD) colacc[tid] = 0.f;
    __syncthreads();

    const float2* pWp2 = (const float2*)pWp;
    const float2* pWn2 = (const float2*)pWn;
    const float2* sfW2 = (const float2*)selfW;
    const float2* mpW2 = (const float2*)mpW;
    const float2* mnW2 = (const float2*)mnW;
    const float2* sm12 = (const float2*)semW1;

    float (*S)[HD] = sb[warp];
    // 0 supA 1 supB 2 psA 3 psB 4 nsA 5 nsB 6 e0A 7 e0B 8 e1A 9 e1B 10 e2A 11 e2B
    {
        float2 sA = ((const float2*)(g_support + nA * HD))[lane];
        float2 sB = ((const float2*)(g_support + nB * HD))[lane];
        S[0][c0] = sA.x; S[0][c1] = sA.y;
        S[1][c0] = sB.x; S[1][c1] = sB.y;
    }
    __syncwarp();

    // ---- phase 1 ----
    float2 pb2  = ((const float2*)pos_b)[lane];
    float2 pbp2 = ((const float2*)pbp)[lane];
    float2 nb2  = ((const float2*)neg_b)[lane];
    float2 pbn2 = ((const float2*)pbn)[lane];
    float2 sfb2 = ((const float2*)selfb)[lane];
    float2 atpA = ((const float2*)(g_att[0] + nA * HD))[lane];
    float2 atpB = ((const float2*)(g_att[0] + nB * HD))[lane];
    float2 atnA = ((const float2*)(g_att[1] + nA * HD))[lane];
    float2 atnB = ((const float2*)(g_att[1] + nB * HD))[lane];
    float apA0 = atpA.x + pb2.x + pbp2.x, apA1 = atpA.y + pb2.y + pbp2.y;
    float apB0 = atpB.x + pb2.x + pbp2.x, apB1 = atpB.y + pb2.y + pbp2.y;
    float anA0 = atnA.x + nb2.x + pbn2.x, anA1 = atnA.y + nb2.y + pbn2.y;
    float anB0 = atnB.x + nb2.x + pbn2.x, anB1 = atnB.y + nb2.y + pbn2.y;
    float svA0 = sfb2.x, svA1 = sfb2.y, svB0 = sfb2.x, svB1 = sfb2.y;
#pragma unroll 4
    for (int k = 0; k < HD; k++) {
        float sA = S[0][k], sBv = S[1][k];
        float2 wp = pWp2[k * 32 + lane];
        float2 wn = pWn2[k * 32 + lane];
        float2 ws = sfW2[k * 32 + lane];
        apA0 += sA * wp.x;  apA1 += sA * wp.y;  apB0 += sBv * wp.x;  apB1 += sBv * wp.y;
        anA0 += sA * wn.x;  anA1 += sA * wn.y;  anB0 += sBv * wn.x;  anB1 += sBv * wn.y;
        svA0 += sA * ws.x;  svA1 += sA * ws.y;  svB0 += sBv * ws.x;  svB1 += sBv * ws.y;
    }
    S[2][c0] = apA0; S[2][c1] = apA1; S[3][c0] = apB0; S[3][c1] = apB1;
    S[4][c0] = anA0; S[4][c1] = anA1; S[5][c0] = anB0; S[5][c1] = anB1;
    __syncwarp();

    // ---- phase 2 ----
    float2 mpb2 = ((const float2*)mpb)[lane];
    float2 mnb2 = ((const float2*)mnb)[lane];
    float spA0 = mpb2.x, spA1 = mpb2.y, spB0 = mpb2.x, spB1 = mpb2.y;
    float snA0 = mnb2.x, snA1 = mnb2.y, snB0 = mnb2.x, snB1 = mnb2.y;
#pragma unroll 4
    for (int k = 0; k < HD; k++) {
        float pA = S[2][k], pB = S[3][k], qA = S[4][k], qB = S[5][k];
        float2 w = mpW2[k * 32 + lane];
        float2 v = mnW2[k * 32 + lane];
        spA0 += pA * w.x; spA1 += pA * w.y; spB0 += pB * w.x; spB1 += pB * w.y;
        snA0 += qA * v.x; snA1 += qA * v.y; snB0 += qB * v.x; snB1 += qB * v.y;
    }
    S[6][c0] = svA0; S[6][c1] = svA1; S[7][c0] = svB0; S[7][c1] = svB1;
    S[8][c0] = spA0; S[8][c1] = spA1; S[9][c0] = spB0; S[9][c1] = spB1;
    S[10][c0] = snA0; S[10][c1] = snA1; S[11][c0] = snB0; S[11][c1] = snB1;
    __syncwarp();

    // ---- phase 3: semantic attention logits ----
    float2 sb12 = ((const float2*)semb1)[lane];
    float tA00 = sb12.x, tA01 = sb12.y, tA10 = sb12.x, tA11 = sb12.y, tA20 = sb12.x, tA21 = sb12.y;
    float tB00 = sb12.x, tB01 = sb12.y, tB10 = sb12.x, tB11 = sb12.y, tB20 = sb12.x, tB21 = sb12.y;
#pragma unroll 4
    for (int k = 0; k < HD; k++) {
        float2 w = sm12[k * 32 + lane];
        float e0A = S[6][k], e0B = S[7][k];
        float e1A = S[8][k], e1B = S[9][k];
        float e2A = S[10][k], e2B = S[11][k];
        tA00 += e0A * w.x; tA01 += e0A * w.y; tB00 += e0B * w.x; tB01 += e0B * w.y;
        tA10 += e1A * w.x; tA11 += e1A * w.y; tB10 += e1B * w.x; tB11 += e1B * w.y;
        tA20 += e2A * w.x; tA21 += e2A * w.y; tB20 += e2B * w.x; tB21 += e2B * w.y;
    }
    float2 w22 = ((const float2*)semW2)[lane];
    float uA0 = tanhfast(tA00) * w22.x + tanhfast(tA01) * w22.y;
    float uA1 = tanhfast(tA10) * w22.x + tanhfast(tA11) * w22.y;
    float uA2 = tanhfast(tA20) * w22.x + tanhfast(tA21) * w22.y;
    float uB0 = tanhfast(tB00) * w22.x + tanhfast(tB01) * w22.y;
    float uB1 = tanhfast(tB10) * w22.x + tanhfast(tB11) * w22.y;
    float uB2 = tanhfast(tB20) * w22.x + tanhfast(tB21) * w22.y;
#pragma unroll
    for (int o = 16; o; o >>= 1) {
        uA0 += __shfl_xor_sync(0xffffffffu, uA0, o);
        uA1 += __shfl_xor_sync(0xffffffffu, uA1, o);
        uA2 += __shfl_xor_sync(0xffffffffu, uA2, o);
        uB0 += __shfl_xor_sync(0xffffffffu, uB0, o);
        uB1 += __shfl_xor_sync(0xffffffffu, uB1, o);
        uB2 += __shfl_xor_sync(0xffffffffu, uB2, o);
    }
    float mA = fmaxf(uA0, fmaxf(uA1, uA2));
    float eA0 = __expf(uA0 - mA), eA1 = __expf(uA1 - mA), eA2 = __expf(uA2 - mA);
    float invA = 1.f / (eA0 + eA1 + eA2);
    float embA0 = (eA0 * svA0 + eA1 * spA0 + eA2 * snA0) * invA;
    float embA1 = (eA0 * svA1 + eA1 * spA1 + eA2 * snA1) * invA;
    float mB = fmaxf(uB0, fmaxf(uB1, uB2));
    float eB0 = __expf(uB0 - mB), eB1 = __expf(uB1 - mB), eB2 = __expf(uB2 - mB);
    float invB = 1.f / (eB0 + eB1 + eB2);
    float embB0 = (eB0 * svB0 + eB1 * spB0 + eB2 * snB0) * invB;
    float embB1 = (eB0 * svB1 + eB1 * spB1 + eB2 * snB1) * invB;

    ((float2*)(g_emb + nA * HD))[lane] = make_float2(embA0, embA1);
    ((float2*)(g_emb + nB * HD))[lane] = make_float2(embB0, embB1);
    atomicAdd(&colacc[c0], embA0 + embB0);
    atomicAdd(&colacc[c1], embA1 + embB1);
    __syncthreads();
    if (tid < HD) atomicAdd(&g_colsum[tid], colacc[tid]);
}

// ---------------- K5: pairnorm + prediction head (warp per node) ----------------
__global__ void final_kernel(const float* __restrict__ predW, const float* __restrict__ predb,
                             float* __restrict__ out) {
    int warp = threadIdx.x >> 5, lane = threadIdx.x & 31;
    int n = blockIdx.x * 4 + warp;
    float invn = 1.0f / NN;
    float x0 = g_emb[n * HD + lane]      - g_colsum[lane]      * invn;
    float x1 = g_emb[n * HD + 32 + lane] - g_colsum[32 + lane] * invn;
    float ss = x0 * x0 + x1 * x1;
    float dt = x0 * predW[lane] + x1 * predW[32 + lane];
#pragma unroll
    for (int o = 16; o; o >>= 1) {
        ss += __shfl_xor_sync(0xffffffffu, ss, o);
        dt += __shfl_xor_sync(0xffffffffu, dt, o);
    }
    if (lane == 0) out[n] = sigm(dt * rsqrtf(1e-6f + ss) + predb[0]);
}

// ---------------- launch ----------------
extern "C" void kernel_launch(void* const* d_in, const int* in_sizes, int n_in,
                              void* d_out, int out_size) {
    (void)in_sizes; (void)n_in; (void)out_size;
    const float* inputs   = (const float*)d_in[0];
    const float* pos_adj  = (const float*)d_in[1];
    const float* neg_adj  = (const float*)d_in[2];
    const float* Wih      = (const float*)d_in[3];
    const float* Whh      = (const float*)d_in[4];
    const float* bih      = (const float*)d_in[5];
    const float* bhh      = (const float*)d_in[6];
    const float* pos_W    = (const float*)d_in[7];
    const float* pos_Wu   = (const float*)d_in[8];
    const float* pos_Wv   = (const float*)d_in[9];
    const float* pos_b    = (const float*)d_in[10];
    const float* pos_projW= (const float*)d_in[11];
    const float* pos_projb= (const float*)d_in[12];
    const float* neg_W    = (const float*)d_in[13];
    const float* neg_Wu   = (const float*)d_in[14];
    const float* neg_Wv   = (const float*)d_in[15];
    const float* neg_b    = (const float*)d_in[16];
    const float* neg_projW= (const float*)d_in[17];
    const float* neg_projb= (const float*)d_in[18];
    const float* self_W   = (const float*)d_in[19];
    const float* self_b   = (const float*)d_in[20];
    const float* mlpp_W   = (const float*)d_in[21];
    const float* mlpp_b   = (const float*)d_in[22];
    const float* mlpn_W   = (const float*)d_in[23];
    const float* mlpn_b   = (const float*)d_in[24];
    const float* sem_W1   = (const float*)d_in[25];
    const float* sem_b1   = (const float*)d_in[26];
    const float* sem_W2   = (const float*)d_in[27];
    const float* pred_W   = (const float*)d_in[28];
    const float* pred_b   = (const float*)d_in[29];

    static int smem_set = 0;
    if (!smem_set) {
        cudaFuncSetAttribute(gru_kernel, cudaFuncAttributeMaxDynamicSharedMemorySize, GRU_SMEM);
        smem_set = 1;
    }

    prep_kernel<<<48, 256>>>(Whh);
    gru_kernel<<<NN / 8, 128, GRU_SMEM>>>(inputs, Wih, bih, bhh,
                                          pos_W, neg_W, pos_Wu, pos_Wv, neg_Wu, neg_Wv);
    attn_kernel<<<dim3(NN, 2), 256>>>(pos_adj, neg_adj);
    comb_kernel<<<NN / 8, 128>>>(pos_b, pos_projW, pos_projb, neg_b, neg_projW, neg_projb,
                                 self_W, self_b, mlpp_W, mlpp_b, mlpn_W, mlpn_b,
                                 sem_W1, sem_b1, sem_W2);
    final_kernel<<<NN / 4, 128>>>(pred_W, pred_b, (float*)d_out);
}

// round 8
// speedup vs baseline: 1.4197x; 1.3051x over previous
#include <cuda_runtime.h>

#define NN 3000
#define TT 20
#define IND 6
#define HD 64
#define NH 8
#define MAXNZ 512

// ---------------- scratch (no allocation allowed) ----------------
__device__ float2 g_Whh2[HD * 192];         // recurrent weights, duplicated pairs [k][row]
__device__ float g_support[NN * HD];        // GRU final hidden
__device__ float g_s[2][NN * HD];           // per-graph head features  [n][h*8+f]
__device__ float g_f1[2][NH * NN];          // source scores  [g][h*N+n]
__device__ float g_f2[2][NH * NN];          // dest scores    [g][h*N+n]
__device__ unsigned g_f1maxI[16];           // encoded global per-(g,h) max of f1
__device__ float g_att[2][NN * HD];         // attention outputs
__device__ float g_emb[NN * HD];            // pre-pairnorm embedding
__device__ float g_colsum[HD];              // column sums for pairnorm mean

__device__ __forceinline__ float sigm(float x) { return 1.0f / (1.0f + __expf(-x)); }
__device__ __forceinline__ float tanhfast(float x) { return 2.0f * sigm(2.0f * x) - 1.0f; }

// order-preserving float<->uint encoding for atomicMax
__device__ __forceinline__ unsigned fenc(float f) {
    unsigned u = __float_as_uint(f);
    return (u & 0x80000000u) ? ~u : (u | 0x80000000u);
}
__device__ __forceinline__ float fdec(unsigned u) {
    return __uint_as_float((u & 0x80000000u) ? (u & 0x7fffffffu) : ~u);
}

// packed f32x2 helpers
__device__ __forceinline__ unsigned long long pk(float lo, float hi) {
    unsigned long long r;
    asm("mov.b64 %0, {%1,%2};" : "=l"(r) : "f"(lo), "f"(hi));
    return r;
}
__device__ __forceinline__ void upk(unsigned long long v, float& lo, float& hi) {
    asm("mov.b64 {%0,%1}, %2;" : "=f"(lo), "=f"(hi) : "l"(v));
}
__device__ __forceinline__ void ffma2(unsigned long long& d, unsigned long long a, unsigned long long b) {
    asm("fma.rn.f32x2 %0, %1, %2, %0;" : "+l"(d) : "l"(a), "l"(b));
}

// ---------------- K0: duplicate Whh pairs + init reductions ----------------
__global__ void prep_kernel(const float* __restrict__ Whh) {
    int i = blockIdx.x * 256 + threadIdx.x;
    if (i < 192 * HD) {
        int r = i >> 6, k = i & 63;
        float w = Whh[i];
        g_Whh2[k * 192 + r] = make_float2(w, w);
    }
    if (blockIdx.x == 0 && threadIdx.x < HD) g_colsum[threadIdx.x] = 0.f;
    if (blockIdx.x == 0 && threadIdx.x < 16) g_f1maxI[threadIdx.x] = 0u;
}

// ---------------- K1: GRU (4 nodes / 64-thread block) + fused head projection ----------------
__global__ void __launch_bounds__(64) gru_kernel(
        const float* __restrict__ x, const float* __restrict__ Wih,
        const float* __restrict__ bih, const float* __restrict__ bhh,
        const float* __restrict__ Wp, const float* __restrict__ Wn,
        const float* __restrict__ Wup, const float* __restrict__ Wvp,
        const float* __restrict__ Wun, const float* __restrict__ Wvn) {
    __shared__ float4 shh4[HD];    // [k] -> 4 nodes hidden
    __shared__ float4 shx4[IND];   // [c] -> 4 nodes input
    float* shxf = (float*)shx4;
    int j = threadIdx.x;           // gate/hidden index 0..63
    int node0 = blockIdx.x * 4;    // 750 blocks

    unsigned long long pwr[IND], pwz[IND], pwn[IND];
#pragma unroll
    for (int c = 0; c < IND; c++) {
        float a = Wih[j * IND + c];
        float b = Wih[(64 + j) * IND + c];
        float d = Wih[(128 + j) * IND + c];
        pwr[c] = pk(a, a); pwz[c] = pk(b, b); pwn[c] = pk(d, d);
    }
    float br  = bih[j] + bhh[j];
    float bz  = bih[64 + j] + bhh[64 + j];
    float bin = bih[128 + j];
    float bhn = bhh[128 + j];
    unsigned long long pbr = pk(br, br), pbz = pk(bz, bz);
    unsigned long long pbi = pk(bin, bin), pbh = pk(bhn, bhn);

    shh4[j] = make_float4(0.f, 0.f, 0.f, 0.f);
    float h0 = 0.f, h1 = 0.f, h2 = 0.f, h3 = 0.f;

    const unsigned long long* w2 = (const unsigned long long*)g_Whh2;

    for (int t = 0; t < TT; t++) {
        if (j < 24) {
            int c = j >> 2, b = j & 3;
            shxf[c * 4 + b] = x[((node0 + b) * TT + t) * IND + c];
        }
        __syncthreads();   // shx ready; prev shh writes visible

        unsigned long long ar01 = pbr, ar23 = pbr;
        unsigned long long az01 = pbz, az23 = pbz;
        unsigned long long an01 = pbi, an23 = pbi;
        unsigned long long gn01 = pbh, gn23 = pbh;

#pragma unroll
        for (int c = 0; c < IND; c++) {
            float4 xv = shx4[c];
            unsigned long long x01 = pk(xv.x, xv.y), x23 = pk(xv.z, xv.w);
            ffma2(ar01, pwr[c], x01); ffma2(ar23, pwr[c], x23);
            ffma2(az01, pwz[c], x01); ffma2(az23, pwz[c], x23);
            ffma2(an01, pwn[c], x01); ffma2(an23, pwn[c], x23);
        }

#pragma unroll 8
        for (int k = 0; k < HD; k++) {
            float4 hv = shh4[k];
            unsigned long long h01 = pk(hv.x, hv.y), h23 = pk(hv.z, hv.w);
            unsigned long long w0 = w2[k * 192 + j];
            unsigned long long w1 = w2[k * 192 + 64 + j];
            unsigned long long wn2 = w2[k * 192 + 128 + j];
            ffma2(ar01, w0, h01);  ffma2(ar23, w0, h23);
            ffma2(az01, w1, h01);  ffma2(az23, w1, h23);
            ffma2(gn01, wn2, h01); ffma2(gn23, wn2, h23);
        }
        __syncthreads();   // all reads of shh done before overwrite

        float a0, a1, a2, a3, z0, z1, z2, z3, n0, n1, n2, n3, g0, g1, g2, g3;
        upk(ar01, a0, a1); upk(ar23, a2, a3);
        upk(az01, z0, z1); upk(az23, z2, z3);
        upk(an01, n0, n1); upk(an23, n2, n3);
        upk(gn01, g0, g1); upk(gn23, g2, g3);

        float r0 = sigm(a0), r1 = sigm(a1), r2 = sigm(a2), r3 = sigm(a3);
        float zz0 = sigm(z0), zz1 = sigm(z1), zz2 = sigm(z2), zz3 = sigm(z3);
        float nv0 = tanhfast(n0 + r0 * g0);
        float nv1 = tanhfast(n1 + r1 * g1);
        float nv2 = tanhfast(n2 + r2 * g2);
        float nv3 = tanhfast(n3 + r3 * g3);
        h0 = (1.f - zz0) * nv0 + zz0 * h0;
        h1 = (1.f - zz1) * nv1 + zz1 * h1;
        h2 = (1.f - zz2) * nv2 + zz2 * h2;
        h3 = (1.f - zz3) * nv3 + zz3 * h3;
        shh4[j] = make_float4(h0, h1, h2, h3);
    }
    __syncthreads();   // h fully written before fused tail reads

    g_support[(node0 + 0) * HD + j] = h0;
    g_support[(node0 + 1) * HD + j] = h1;
    g_support[(node0 + 2) * HD + j] = h2;
    g_support[(node0 + 3) * HD + j] = h3;

    // ------ fused head projection: s = h @ W, f1/f2, global f1 max ------
    int hh = j >> 3, f = j & 7;
    const float* hsm = (const float*)shh4;   // [k*4 + b]
#pragma unroll
    for (int g = 0; g < 2; g++) {
        const float* W  = g ? Wn  : Wp;
        float wu = (g ? Wun : Wup)[hh * 8 + f];
        float wv = (g ? Wvn : Wvp)[hh * 8 + f];
        float acc[4] = {0.f, 0.f, 0.f, 0.f};
#pragma unroll 4
        for (int k = 0; k < HD; k++) {
            float w = W[k * HD + j];
#pragma unroll
            for (int b = 0; b < 4; b++) acc[b] += hsm[k * 4 + b] * w;
        }
#pragma unroll
        for (int b = 0; b < 4; b++) {
            int n = node0 + b;
            g_s[g][n * HD + j] = acc[b];
            float t1 = acc[b] * wu, t2 = acc[b] * wv;
#pragma unroll
            for (int o = 4; o; o >>= 1) {
                t1 += __shfl_xor_sync(0xffffffffu, t1, o);
                t2 += __shfl_xor_sync(0xffffffffu, t2, o);
            }
            if (f == 0) {
                g_f1[g][hh * NN + n] = t1;
                g_f2[g][hh * NN + n] = t2;
                atomicMax(&g_f1maxI[g * 8 + hh], fenc(t1));
            }
        }
    }
}

// ---------------- K3: sparse masked attention, single pass (grid: [N, 2]) ----------------
__global__ void attn_kernel(const float* __restrict__ adj0, const float* __restrict__ adj1) {
    int i = blockIdx.x, g = blockIdx.y;
    const float* row = (g ? adj1 : adj0) + (size_t)i * NN;
    __shared__ int cnt;
    __shared__ short idx[MAXNZ];
    int tid = threadIdx.x, lane = tid & 31;
    if (tid == 0) cnt = 0;

    // prefetch the whole row slice to registers (MLP=3) before compaction
    const float4* row4 = (const float4*)row;   // N=3000 divisible by 4
    float4 v[3];
#pragma unroll
    for (int it = 0; it < 3; it++) {
        int q = it * 256 + tid;
        v[it] = (q < NN / 4) ? row4[q] : make_float4(0.f, 0.f, 0.f, 0.f);
    }
    __syncthreads();

#pragma unroll
    for (int it = 0; it < 3; it++) {
        int q = it * 256 + tid;
#pragma unroll
        for (int c = 0; c < 4; c++) {
            float val = (c == 0) ? v[it].x : (c == 1) ? v[it].y : (c == 2) ? v[it].z : v[it].w;
            unsigned bal = __ballot_sync(0xffffffffu, val != 0.f);
            if (bal) {
                int leader = __ffs(bal) - 1;
                int base;
                if (lane == leader) base = atomicAdd(&cnt, __popc(bal));
                base = __shfl_sync(0xffffffffu, base, leader);
                if (val != 0.f) {
                    int p = base + __popc(bal & ((1u << lane) - 1u));
                    if (p < MAXNZ) idx[p] = (short)(4 * q + c);
                }
            }
        }
    }
    __syncthreads();
    int m = min(cnt, MAXNZ);

    int h = tid >> 5;                         // warp = head
    const float* f1h = g_f1[g] + h * NN;
    float f2v = g_f2[g][h * NN + i];
    // shift M >= max over row nonzeros (leaky monotone; softmax shift-invariant)
    float Mv = fdec(g_f1maxI[g * 8 + h]) + f2v;
    Mv = Mv >= 0.f ? Mv : 0.2f * Mv;
    const float* sb = g_s[g];

    float se = 0.f;
    float acc[8] = {0, 0, 0, 0, 0, 0, 0, 0};
    for (int k = lane; k < m; k += 32) {
        int j = idx[k];
        float vv = f1h[j] + f2v;
        vv = vv >= 0.f ? vv : 0.2f * vv;
        float e = __expf(vv - Mv);
        se += e;
        const float4* sp = (const float4*)(sb + j * HD + h * 8);
        float4 a = sp[0], bb = sp[1];
        acc[0] += e * a.x;  acc[1] += e * a.y;  acc[2] += e * a.z;  acc[3] += e * a.w;
        acc[4] += e * bb.x; acc[5] += e * bb.y; acc[6] += e * bb.z; acc[7] += e * bb.w;
    }
#pragma unroll
    for (int o = 16; o; o >>= 1) {
        se += __shfl_xor_sync(0xffffffffu, se, o);
#pragma unroll
        for (int f = 0; f < 8; f++) acc[f] += __shfl_xor_sync(0xffffffffu, acc[f], o);
    }
    if (lane == 0) {
        float inv = se > 0.f ? 1.0f / se : 0.f;   // empty row -> zeros (matches ref mask)
        float* o2 = g_att[g] + i * HD + h * 8;
#pragma unroll
        for (int f = 0; f < 8; f++) o2[f] = acc[f] * inv;
    }
}

// ---------------- K4: warp-per-2-nodes, float2 channel pairing (grid: N/8, block 128) ----------------
__global__ void __launch_bounds__(128) comb_kernel(
        const float* __restrict__ pos_b, const float* __restrict__ pWp, const float* __restrict__ pbp,
        const float* __restrict__ neg_b, const float* __restrict__ pWn, const float* __restrict__ pbn,
        const float* __restrict__ selfW, const float* __restrict__ selfb,
        const float* __restrict__ mpW, const float* __restrict__ mpb,
        const float* __restrict__ mnW, const float* __restrict__ mnb,
        const float* __restrict__ semW1, const float* __restrict__ semb1,
        const float* __restrict__ semW2) {
    __shared__ float sb[4][12][HD];     // per-warp staging
    __shared__ float colacc[HD];
    int tid = threadIdx.x, warp = tid >> 5, lane = tid & 31;
    int nA = blockIdx.x * 8 + warp * 2;   // 375*8 = 3000 exact
    int nB = nA + 1;
    int c0 = 2 * lane, c1 = 2 * lane + 1;

    if (tid < HD) colacc[tid] = 0.f;
    __syncthreads();

    const float2* pWp2 = (const float2*)pWp;
    const float2* pWn2 = (const float2*)pWn;
    const float2* sfW2 = (const float2*)selfW;
    const float2* mpW2 = (const float2*)mpW;
    const float2* mnW2 = (const float2*)mnW;
    const float2* sm12 = (const float2*)semW1;

    float (*S)[HD] = sb[warp];
    // 0 supA 1 supB 2 psA 3 psB 4 nsA 5 nsB 6 e0A 7 e0B 8 e1A 9 e1B 10 e2A 11 e2B
    {
        float2 sA = ((const float2*)(g_support + nA * HD))[lane];
        float2 sB = ((const float2*)(g_support + nB * HD))[lane];
        S[0][c0] = sA.x; S[0][c1] = sA.y;
        S[1][c0] = sB.x; S[1][c1] = sB.y;
    }
    __syncwarp();

    // ---- phase 1 ----
    float2 pb2  = ((const float2*)pos_b)[lane];
    float2 pbp2 = ((const float2*)pbp)[lane];
    float2 nb2  = ((const float2*)neg_b)[lane];
    float2 pbn2 = ((const float2*)pbn)[lane];
    float2 sfb2 = ((const float2*)selfb)[lane];
    float2 atpA = ((const float2*)(g_att[0] + nA * HD))[lane];
    float2 atpB = ((const float2*)(g_att[0] + nB * HD))[lane];
    float2 atnA = ((const float2*)(g_att[1] + nA * HD))[lane];
    float2 atnB = ((const float2*)(g_att[1] + nB * HD))[lane];
    float apA0 = atpA.x + pb2.x + pbp2.x, apA1 = atpA.y + pb2.y + pbp2.y;
    float apB0 = atpB.x + pb2.x + pbp2.x, apB1 = atpB.y + pb2.y + pbp2.y;
    float anA0 = atnA.x + nb2.x + pbn2.x, anA1 = atnA.y + nb2.y + pbn2.y;
    float anB0 = atnB.x + nb2.x + pbn2.x, anB1 = atnB.y + nb2.y + pbn2.y;
    float svA0 = sfb2.x, svA1 = sfb2.y, svB0 = sfb2.x, svB1 = sfb2.y;
#pragma unroll 4
    for (int k = 0; k < HD; k++) {
        float sA = S[0][k], sBv = S[1][k];
        float2 wp = pWp2[k * 32 + lane];
        float2 wn = pWn2[k * 32 + lane];
        float2 ws = sfW2[k * 32 + lane];
        apA0 += sA * wp.x;  apA1 += sA * wp.y;  apB0 += sBv * wp.x;  apB1 += sBv * wp.y;
        anA0 += sA * wn.x;  anA1 += sA * wn.y;  anB0 += sBv * wn.x;  anB1 += sBv * wn.y;
        svA0 += sA * ws.x;  svA1 += sA * ws.y;  svB0 += sBv * ws.x;  svB1 += sBv * ws.y;
    }
    S[2][c0] = apA0; S[2][c1] = apA1; S[3][c0] = apB0; S[3][c1] = apB1;
    S[4][c0] = anA0; S[4][c1] = anA1; S[5][c0] = anB0; S[5][c1] = anB1;
    __syncwarp();

    // ---- phase 2 ----
    float2 mpb2 = ((const float2*)mpb)[lane];
    float2 mnb2 = ((const float2*)mnb)[lane];
    float spA0 = mpb2.x, spA1 = mpb2.y, spB0 = mpb2.x, spB1 = mpb2.y;
    float snA0 = mnb2.x, snA1 = mnb2.y, snB0 = mnb2.x, snB1 = mnb2.y;
#pragma unroll 4
    for (int k = 0; k < HD; k++) {
        float pA = S[2][k], pB = S[3][k], qA = S[4][k], qB = S[5][k];
        float2 w = mpW2[k * 32 + lane];
        float2 v = mnW2[k * 32 + lane];
        spA0 += pA * w.x; spA1 += pA * w.y; spB0 += pB * w.x; spB1 += pB * w.y;
        snA0 += qA * v.x; snA1 += qA * v.y; snB0 += qB * v.x; snB1 += qB * v.y;
    }
    S[6][c0] = svA0; S[6][c1] = svA1; S[7][c0] = svB0; S[7][c1] = svB1;
    S[8][c0] = spA0; S[8][c1] = spA1; S[9][c0] = spB0; S[9][c1] = spB1;
    S[10][c0] = snA0; S[10][c1] = snA1; S[11][c0] = snB0; S[11][c1] = snB1;
    __syncwarp();

    // ---- phase 3: semantic attention logits ----
    float2 sb12 = ((const float2*)semb1)[lane];
    float tA00 = sb12.x, tA01 = sb12.y, tA10 = sb12.x, tA11 = sb12.y, tA20 = sb12.x, tA21 = sb12.y;
    float tB00 = sb12.x, tB01 = sb12.y, tB10 = sb12.x, tB11 = sb12.y, tB20 = sb12.x, tB21 = sb12.y;
#pragma unroll 4
    for (int k = 0; k < HD; k++) {
        float2 w = sm12[k * 32 + lane];
        float e0A = S[6][k], e0B = S[7][k];
        float e1A = S[8][k], e1B = S[9][k];
        float e2A = S[10][k], e2B = S[11][k];
        tA00 += e0A * w.x; tA01 += e0A * w.y; tB00 += e0B * w.x; tB01 += e0B * w.y;
        tA10 += e1A * w.x; tA11 += e1A * w.y; tB10 += e1B * w.x; tB11 += e1B * w.y;
        tA20 += e2A * w.x; tA21 += e2A * w.y; tB20 += e2B * w.x; tB21 += e2B * w.y;
    }
    float2 w22 = ((const float2*)semW2)[lane];
    float uA0 = tanhfast(tA00) * w22.x + tanhfast(tA01) * w22.y;
    float uA1 = tanhfast(tA10) * w22.x + tanhfast(tA11) * w22.y;
    float uA2 = tanhfast(tA20) * w22.x + tanhfast(tA21) * w22.y;
    float uB0 = tanhfast(tB00) * w22.x + tanhfast(tB01) * w22.y;
    float uB1 = tanhfast(tB10) * w22.x + tanhfast(tB11) * w22.y;
    float uB2 = tanhfast(tB20) * w22.x + tanhfast(tB21) * w22.y;
#pragma unroll
    for (int o = 16; o; o >>= 1) {
        uA0 += __shfl_xor_sync(0xffffffffu, uA0, o);
        uA1 += __shfl_xor_sync(0xffffffffu, uA1, o);
        uA2 += __shfl_xor_sync(0xffffffffu, uA2, o);
        uB0 += __shfl_xor_sync(0xffffffffu, uB0, o);
        uB1 += __shfl_xor_sync(0xffffffffu, uB1, o);
        uB2 += __shfl_xor_sync(0xffffffffu, uB2, o);
    }
    float mA = fmaxf(uA0, fmaxf(uA1, uA2));
    float eA0 = __expf(uA0 - mA), eA1 = __expf(uA1 - mA), eA2 = __expf(uA2 - mA);
    float invA = 1.f / (eA0 + eA1 + eA2);
    float embA0 = (eA0 * svA0 + eA1 * spA0 + eA2 * snA0) * invA;
    float embA1 = (eA0 * svA1 + eA1 * spA1 + eA2 * snA1) * invA;
    float mB = fmaxf(uB0, fmaxf(uB1, uB2));
    float eB0 = __expf(uB0 - mB), eB1 = __expf(uB1 - mB), eB2 = __expf(uB2 - mB);
    float invB = 1.f / (eB0 + eB1 + eB2);
    float embB0 = (eB0 * svB0 + eB1 * spB0 + eB2 * snB0) * invB;
    float embB1 = (eB0 * svB1 + eB1 * spB1 + eB2 * snB1) * invB;

    ((float2*)(g_emb + nA * HD))[lane] = make_float2(embA0, embA1);
    ((float2*)(g_emb + nB * HD))[lane] = make_float2(embB0, embB1);
    atomicAdd(&colacc[c0], embA0 + embB0);
    atomicAdd(&colacc[c1], embA1 + embB1);
    __syncthreads();
    if (tid < HD) atomicAdd(&g_colsum[tid], colacc[tid]);
}

// ---------------- K5: pairnorm + prediction head (warp per node) ----------------
__global__ void final_kernel(const float* __restrict__ predW, const float* __restrict__ predb,
                             float* __restrict__ out) {
    int warp = threadIdx.x >> 5, lane = threadIdx.x & 31;
    int n = blockIdx.x * 4 + warp;
    float invn = 1.0f / NN;
    float x0 = g_emb[n * HD + lane]      - g_colsum[lane]      * invn;
    float x1 = g_emb[n * HD + 32 + lane] - g_colsum[32 + lane] * invn;
    float ss = x0 * x0 + x1 * x1;
    float dt = x0 * predW[lane] + x1 * predW[32 + lane];
#pragma unroll
    for (int o = 16; o; o >>= 1) {
        ss += __shfl_xor_sync(0xffffffffu, ss, o);
        dt += __shfl_xor_sync(0xffffffffu, dt, o);
    }
    if (lane == 0) out[n] = sigm(dt * rsqrtf(1e-6f + ss) + predb[0]);
}

// ---------------- launch ----------------
extern "C" void kernel_launch(void* const* d_in, const int* in_sizes, int n_in,
                              void* d_out, int out_size) {
    (void)in_sizes; (void)n_in; (void)out_size;
    const float* inputs   = (const float*)d_in[0];
    const float* pos_adj  = (const float*)d_in[1];
    const float* neg_adj  = (const float*)d_in[2];
    const float* Wih      = (const float*)d_in[3];
    const float* Whh      = (const float*)d_in[4];
    const float* bih      = (const float*)d_in[5];
    const float* bhh      = (const float*)d_in[6];
    const float* pos_W    = (const float*)d_in[7];
    const float* pos_Wu   = (const float*)d_in[8];
    const float* pos_Wv   = (const float*)d_in[9];
    const float* pos_b    = (const float*)d_in[10];
    const float* pos_projW= (const float*)d_in[11];
    const float* pos_projb= (const float*)d_in[12];
    const float* neg_W    = (const float*)d_in[13];
    const float* neg_Wu   = (const float*)d_in[14];
    const float* neg_Wv   = (const float*)d_in[15];
    const float* neg_b    = (const float*)d_in[16];
    const float* neg_projW= (const float*)d_in[17];
    const float* neg_projb= (const float*)d_in[18];
    const float* self_W   = (const float*)d_in[19];
    const float* self_b   = (const float*)d_in[20];
    const float* mlpp_W   = (const float*)d_in[21];
    const float* mlpp_b   = (const float*)d_in[22];
    const float* mlpn_W   = (const float*)d_in[23];
    const float* mlpn_b   = (const float*)d_in[24];
    const float* sem_W1   = (const float*)d_in[25];
    const float* sem_b1   = (const float*)d_in[26];
    const float* sem_W2   = (const float*)d_in[27];
    const float* pred_W   = (const float*)d_in[28];
    const float* pred_b   = (const float*)d_in[29];

    prep_kernel<<<48, 256>>>(Whh);
    gru_kernel<<<NN / 4, 64>>>(inputs, Wih, bih, bhh,
                               pos_W, neg_W, pos_Wu, pos_Wv, neg_Wu, neg_Wv);
    attn_kernel<<<dim3(NN, 2), 256>>>(pos_adj, neg_adj);
    comb_kernel<<<NN / 8, 128>>>(pos_b, pos_projW, pos_projb, neg_b, neg_projW, neg_projb,
                                 self_W, self_b, mlpp_W, mlpp_b, mlpn_W, mlpn_b,
                                 sem_W1, sem_b1, sem_W2);
    final_kernel<<<NN / 4, 128>>>(pred_W, pred_b, (float*)d_out);
}